// round 10
// baseline (speedup 1.0000x reference)
#include <cuda_runtime.h>
#include <cuda_bf16.h>
#include <cstdint>

#define D_A      1024
#define NEXP     64
#define BATCH    256
#define POOL_DIM 33792
#define U_END    16384
#define V_END    32768
#define KP       1152     /* padded row stride (elems) for bf16 S / BmatT */
#define LN_EPS   1e-5f

#define NK1 16            /* 1024/64 */
#define NK2 17            /* 1088/64 */
#define A_STG1 8192       /* 64 rows x 128B */
#define B_STG1 8192
#define A_STG2 4096       /* 32 rows x 128B */
#define B_STG2 8192       /* 64 rows x 128B */
#define EP 68             /* epilogue stage stride (floats) */

// ---------------- scratch ----------------
__device__ __align__(128) __nv_bfloat16 g_hA16[BATCH * D_A];            // 512KB
__device__ __align__(128) __nv_bfloat16 g_B1[(size_t)2048 * D_A];       // 4MB  [j][k] j: W rows | V rows
__device__ __align__(128) __nv_bfloat16 g_BmatT16[(size_t)1024 * KP];   // 2.25MB [c][k]
__device__ __align__(128) __nv_bfloat16 g_S16[(size_t)BATCH * KP];      // 576KB [b][k]
__device__ __align__(128) float  g_P[BATCH * 1024];
__device__ __align__(128) float  g_X[BATCH * 1024];
__device__ __align__(128) float2 g_part[BATCH * 16];                    // [row][bn]

// ---------------- helpers ----------------
__device__ __forceinline__ uint32_t smem_u32(const void* p) {
    uint32_t a;
    asm("{ .reg .u64 t; cvta.to.shared.u64 t, %1; cvt.u32.u64 %0, t; }" : "=r"(a) : "l"(p));
    return a;
}
__device__ __forceinline__ uint32_t swz(uint32_t off) { return off ^ ((off >> 3) & 0x70); }
__device__ __forceinline__ void cpa16(uint32_t saddr, const void* g) {
    asm volatile("cp.async.cg.shared.global [%0], [%1], 16;\n" :: "r"(saddr), "l"(g));
}
__device__ __forceinline__ void cp_commit() { asm volatile("cp.async.commit_group;\n"); }
template<int N> __device__ __forceinline__ void cp_wait() {
    asm volatile("cp.async.wait_group %0;\n" :: "n"(N));
}
#define LDSM4(R, addr) \
    asm volatile("ldmatrix.sync.aligned.m8n8.x4.shared.b16 {%0,%1,%2,%3}, [%4];" \
        : "=r"((R)[0]), "=r"((R)[1]), "=r"((R)[2]), "=r"((R)[3]) : "r"(addr))
__device__ __forceinline__ void mma_bf16(float* c, const uint32_t* a, uint32_t b0, uint32_t b1) {
    asm volatile(
        "mma.sync.aligned.m16n8k16.row.col.f32.bf16.bf16.f32 "
        "{%0,%1,%2,%3}, {%4,%5,%6,%7}, {%8,%9}, {%0,%1,%2,%3};\n"
        : "+f"(c[0]), "+f"(c[1]), "+f"(c[2]), "+f"(c[3])
        : "r"(a[0]), "r"(a[1]), "r"(a[2]), "r"(a[3]), "r"(b0), "r"(b1));
}
__device__ __forceinline__ uint32_t pack_bf2(float x, float y) {
    __nv_bfloat162 h = __floats2bfloat162_rn(x, y);
    return *reinterpret_cast<uint32_t*>(&h);
}

// ---------------- k0: convert + prep (145 blocks x 256) ---------------------
// bid 0..15: U transpose (64 c-rows each) + bias cols -> g_BmatT16
// bid 16:    alpha cols of g_S16
// bid 17..144 (cid): 16 rows of g_B1 (W|V -> bf16) + 2 rows of g_hA16
__global__ void __launch_bounds__(256) k0_kernel(const float* __restrict__ hA,
                                                 const float* __restrict__ pool,
                                                 const float* __restrict__ alpha,
                                                 const float* __restrict__ W) {
    __shared__ float sf[8448];
    const int tid = threadIdx.x;
    const int bid = blockIdx.x;
    if (bid < 16) {
        for (int half = 0; half < 2; half++) {
            const int c0 = bid * 64 + half * 32;
            for (int ng = 0; ng < 4; ng++) {
                #pragma unroll
                for (int it = 0; it < 8; it++) {
                    int e = tid + it * 256;
                    int nl = e >> 7, i4 = e & 127;
                    const float4* src = (const float4*)(pool + (size_t)(ng * 16 + nl) * POOL_DIM + c0 * 16) + i4;
                    *(float4*)(sf + nl * 528 + i4 * 4) = *src;
                }
                __syncthreads();
                #pragma unroll 8
                for (int it = 0; it < 32; it++) {
                    int e = tid + it * 256;
                    int cl = e >> 8, j = e & 255;
                    int nl = j >> 4, r = j & 15;
                    g_BmatT16[(size_t)(c0 + cl) * KP + ng * 256 + j] =
                        __float2bfloat16(sf[nl * 528 + cl * 16 + r]);
                }
                __syncthreads();
            }
            #pragma unroll
            for (int it = 0; it < 8; it++) {
                int e = tid + it * 256;
                int n = e >> 5, cl = e & 31;
                sf[n * 33 + cl] = pool[(size_t)n * POOL_DIM + V_END + c0 + cl];
            }
            __syncthreads();
            #pragma unroll
            for (int it = 0; it < 8; it++) {
                int e = tid + it * 256;
                int cl = e >> 6, n = e & 63;
                g_BmatT16[(size_t)(c0 + cl) * KP + 1024 + n] = __float2bfloat16(sf[n * 33 + cl]);
            }
            __syncthreads();
        }
    } else if (bid == 16) {
        #pragma unroll 8
        for (int it = 0; it < 64; it++) {
            int e = tid + it * 256;
            int b = e >> 6, n = e & 63;
            g_S16[(size_t)b * KP + 1024 + n] = __float2bfloat16(alpha[b * NEXP + n]);
        }
    } else {
        const int cid = bid - 17;
        #pragma unroll 4
        for (int it = 0; it < 16; it++) {
            int e = tid + it * 256;
            int rr = e >> 8, i4 = e & 255;
            int j = cid * 16 + rr;
            const float* src = (j < 1024)
                ? (W + (size_t)j * D_A)
                : (pool + (size_t)((j - 1024) >> 4) * POOL_DIM + U_END + (size_t)((j - 1024) & 15) * D_A);
            float4 v = ((const float4*)src)[i4];
            *(uint2*)((char*)g_B1 + (size_t)j * 2048 + i4 * 8) =
                make_uint2(pack_bf2(v.x, v.y), pack_bf2(v.z, v.w));
        }
        #pragma unroll
        for (int it = 0; it < 2; it++) {
            int e = tid + it * 256;
            int rr = e >> 8, i4 = e & 255;
            int row = cid * 2 + rr;
            float4 v = ((const float4*)(hA + (size_t)row * D_A))[i4];
            *(uint2*)((char*)g_hA16 + (size_t)row * 2048 + i4 * 8) =
                make_uint2(pack_bf2(v.x, v.y), pack_bf2(v.z, v.w));
        }
    }
}

// ---------------- k1: GEMM1 bf16, 64x64 tiles, 128 CTAs ---------------------
// C[256,2048] = hA16 * g_B1^T ; cols<1024 -> g_P, cols>=1024 -> g_S16*alpha
__global__ void __launch_bounds__(256) k1_kernel(const float* __restrict__ alpha) {
    __shared__ __align__(128) char smem_all[49152];   // 3 stages x (8K A + 8K B)
    const uint32_t sb = smem_u32(smem_all);
    const int bid = blockIdx.x;
    const int bm = bid >> 5;          // 0..3
    const int bn = bid & 31;          // 0..31
    const int tid = threadIdx.x;
    const int lane = tid & 31, warp = tid >> 5;
    const int wm = warp & 1;          // 2 x 32 rows
    const int wn = warp >> 1;         // 4 x 16 cols
    const int g = lane >> 2, tig = lane & 3;

    const uint32_t sbA = sb;
    const uint32_t sbB = sb + 3 * A_STG1;

    const char* aSrc[2]; uint32_t aDst[2];
    const char* bSrc[2]; uint32_t bDst[2];
    #pragma unroll
    for (int q = 0; q < 2; q++) {
        int id = tid + q * 256;
        int row = id >> 3, c8 = id & 7;
        aSrc[q] = (const char*)g_hA16 + (size_t)(bm * 64 + row) * 2048 + c8 * 16;
        aDst[q] = swz(row * 128 + c8 * 16);
        bSrc[q] = (const char*)g_B1 + (size_t)(bn * 64 + row) * 2048 + c8 * 16;
        bDst[q] = aDst[q];
    }
    auto fill = [&](int s, int kc) {
        const int off = kc * 128;
        #pragma unroll
        for (int q = 0; q < 2; q++) {
            cpa16(sbA + s * A_STG1 + aDst[q], aSrc[q] + off);
            cpa16(sbB + s * B_STG1 + bDst[q], bSrc[q] + off);
        }
    };

    uint32_t aBase[2], aXor[2], bBase, bXor;
    const uint32_t half16 = ((lane >> 4) & 1) * 16;
    #pragma unroll
    for (int im = 0; im < 2; im++) {
        int r = wm * 32 + im * 16 + (lane & 15);
        aBase[im] = r * 128; aXor[im] = (r & 7) << 4;
    }
    {
        int r = wn * 16 + (lane & 15);
        bBase = r * 128; bXor = (r & 7) << 4;
    }

    float acc[2][2][4];
    #pragma unroll
    for (int i = 0; i < 2; i++)
        #pragma unroll
        for (int j = 0; j < 2; j++)
            #pragma unroll
            for (int e = 0; e < 4; e++) acc[i][j][e] = 0.f;

    fill(0, 0); cp_commit(); fill(1, 1); cp_commit();

    int s = 0;
    for (int i = 0; i < NK1; i++) {
        cp_wait<1>();
        __syncthreads();
        if (i + 2 < NK1) fill((i + 2) % 3, i + 2);
        cp_commit();
        const uint32_t sA = sbA + s * A_STG1;
        const uint32_t sB = sbB + s * B_STG1;
        #pragma unroll
        for (int kk = 0; kk < 4; kk++) {
            uint32_t a[2][4], bq[4];
            #pragma unroll
            for (int im = 0; im < 2; im++)
                LDSM4(a[im], sA + aBase[im] + ((kk * 32 + half16) ^ aXor[im]));
            LDSM4(bq, sB + bBase + ((kk * 32 + half16) ^ bXor));
            #pragma unroll
            for (int im = 0; im < 2; im++) {
                mma_bf16(acc[im][0], a[im], bq[0], bq[2]);
                mma_bf16(acc[im][1], a[im], bq[1], bq[3]);
            }
        }
        s = (s == 2) ? 0 : s + 1;
    }
    __syncthreads();

    float* se = (float*)smem_all;
    #pragma unroll
    for (int im = 0; im < 2; im++)
        #pragma unroll
        for (int jb = 0; jb < 2; jb++) {
            int r0 = wm * 32 + im * 16 + g;
            int c  = wn * 16 + jb * 8 + 2 * tig;
            se[r0 * EP + c]           = acc[im][jb][0];
            se[r0 * EP + c + 1]       = acc[im][jb][1];
            se[(r0 + 8) * EP + c]     = acc[im][jb][2];
            se[(r0 + 8) * EP + c + 1] = acc[im][jb][3];
        }
    __syncthreads();
    #pragma unroll
    for (int it = 0; it < 4; it++) {
        int id = tid + it * 256;
        int row = id >> 4, c4 = id & 15;
        float4 v = *(const float4*)(se + row * EP + c4 * 4);
        int rowg = bm * 64 + row;
        if (bn < 16) {
            ((float4*)g_P)[(size_t)rowg * 256 + bn * 16 + c4] = v;
        } else {
            int n = (bn - 16) * 4 + (c4 >> 2);
            float a = alpha[rowg * NEXP + n];
            *(uint2*)((char*)g_S16 + ((size_t)rowg * KP + (bn - 16) * 64 + c4 * 4) * 2) =
                make_uint2(pack_bf2(v.x * a, v.y * a), pack_bf2(v.z * a, v.w * a));
        }
    }
}

// ---------------- k2: GEMM2 bf16, 32x64 tiles, 128 CTAs ---------------------
// X = hA + gamma*(S16 @ BmatT16^T + P + b_base)
__global__ void __launch_bounds__(256) k2_kernel(const float* __restrict__ hA,
                                                 const float* __restrict__ bbase,
                                                 const float* __restrict__ gamma_p) {
    __shared__ __align__(128) char smem_all[49152];   // 4 stages x (4K A + 8K B)
    const uint32_t sb = smem_u32(smem_all);
    const int bid = blockIdx.x;
    const int bm = bid >> 4;          // 0..7 (32-row tiles)
    const int bn = bid & 15;          // 0..15 (64-col tiles)
    const int tid = threadIdx.x;
    const int lane = tid & 31, warp = tid >> 5;
    const int wm = warp & 1;          // 2 x 16 rows
    const int wn = warp >> 1;         // 4 x 16 cols
    const int g = lane >> 2, tig = lane & 3;

    const uint32_t sbA = sb;
    const uint32_t sbB = sb + 4 * A_STG2;

    const char* aSrc; uint32_t aDst;
    {
        int row = tid >> 3, c8 = tid & 7;
        aSrc = (const char*)g_S16 + (size_t)(bm * 32 + row) * (KP * 2) + c8 * 16;
        aDst = swz(row * 128 + c8 * 16);
    }
    const char* bSrc[2]; uint32_t bDst[2];
    #pragma unroll
    for (int q = 0; q < 2; q++) {
        int id = tid + q * 256;
        int row = id >> 3, c8 = id & 7;
        bSrc[q] = (const char*)g_BmatT16 + (size_t)(bn * 64 + row) * (KP * 2) + c8 * 16;
        bDst[q] = swz(row * 128 + c8 * 16);
    }
    auto fill = [&](int s, int kc) {
        const int off = kc * 128;
        cpa16(sbA + s * A_STG2 + aDst, aSrc + off);
        #pragma unroll
        for (int q = 0; q < 2; q++)
            cpa16(sbB + s * B_STG2 + bDst[q], bSrc[q] + off);
    };

    uint32_t aBase, aXor, bBase, bXor;
    const uint32_t half16 = ((lane >> 4) & 1) * 16;
    {
        int r = wm * 16 + (lane & 15);
        aBase = r * 128; aXor = (r & 7) << 4;
    }
    {
        int r = wn * 16 + (lane & 15);
        bBase = r * 128; bXor = (r & 7) << 4;
    }

    float acc[2][4];
    #pragma unroll
    for (int j = 0; j < 2; j++)
        #pragma unroll
        for (int e = 0; e < 4; e++) acc[j][e] = 0.f;

    fill(0, 0); cp_commit(); fill(1, 1); cp_commit(); fill(2, 2); cp_commit();

    for (int i = 0; i < NK2; i++) {
        cp_wait<2>();
        __syncthreads();
        if (i + 3 < NK2) fill((i + 3) & 3, i + 3);
        cp_commit();
        const int s = i & 3;
        const uint32_t sA = sbA + s * A_STG2;
        const uint32_t sB = sbB + s * B_STG2;
        #pragma unroll
        for (int kk = 0; kk < 4; kk++) {
            uint32_t a[4], bq[4];
            LDSM4(a, sA + aBase + ((kk * 32 + half16) ^ aXor));
            LDSM4(bq, sB + bBase + ((kk * 32 + half16) ^ bXor));
            mma_bf16(acc[0], a, bq[0], bq[2]);
            mma_bf16(acc[1], a, bq[1], bq[3]);
        }
    }
    __syncthreads();

    float* se = (float*)smem_all;
    #pragma unroll
    for (int jb = 0; jb < 2; jb++) {
        int r0 = wm * 16 + g;
        int c  = wn * 16 + jb * 8 + 2 * tig;
        se[r0 * EP + c]           = acc[jb][0];
        se[r0 * EP + c + 1]       = acc[jb][1];
        se[(r0 + 8) * EP + c]     = acc[jb][2];
        se[(r0 + 8) * EP + c + 1] = acc[jb][3];
    }
    __syncthreads();
    const float gam = *gamma_p;
    #pragma unroll
    for (int it = 0; it < 2; it++) {
        int id = tid + it * 256;
        int row = id >> 4, c4 = id & 15;
        float4 v = *(const float4*)(se + row * EP + c4 * 4);
        int rowg = bm * 32 + row;
        int cc4 = bn * 16 + c4;
        float4 p4 = ((const float4*)g_P)[(size_t)rowg * 256 + cc4];
        float4 b4 = ((const float4*)bbase)[cc4];
        float4 h4 = ((const float4*)hA)[(size_t)rowg * 256 + cc4];
        float4 x;
        x.x = h4.x + gam * (v.x + p4.x + b4.x);
        x.y = h4.y + gam * (v.y + p4.y + b4.y);
        x.z = h4.z + gam * (v.z + p4.z + b4.z);
        x.w = h4.w + gam * (v.w + p4.w + b4.w);
        ((float4*)g_X)[(size_t)rowg * 256 + cc4] = x;
        float s2  = x.x + x.y + x.z + x.w;
        float ss2 = x.x * x.x + x.y * x.y + x.z * x.z + x.w * x.w;
        #pragma unroll
        for (int off = 8; off; off >>= 1) {
            s2  += __shfl_xor_sync(0xffffffffu, s2, off);
            ss2 += __shfl_xor_sync(0xffffffffu, ss2, off);
        }
        if ((tid & 15) == 0) g_part[rowg * 16 + bn] = make_float2(s2, ss2);
    }
}

// ---------------- LayerNorm: warp per row, normalize-only ----------------
__global__ void __launch_bounds__(256) ln_kernel(const float* __restrict__ lns,
                                                 const float* __restrict__ lnb,
                                                 float* __restrict__ out) {
    const int tid = threadIdx.x;
    const int lane = tid & 31;
    const int row = blockIdx.x * 8 + (tid >> 5);
    float s = 0.f, ss = 0.f;
    if (lane < 16) {
        float2 p = g_part[row * 16 + lane];
        s = p.x; ss = p.y;
    }
    #pragma unroll
    for (int off = 16; off; off >>= 1) {
        s  += __shfl_xor_sync(0xffffffffu, s, off);
        ss += __shfl_xor_sync(0xffffffffu, ss, off);
    }
    const float mean = s * (1.f / 1024.f);
    const float inv  = rsqrtf(ss * (1.f / 1024.f) - mean * mean + LN_EPS);
    #pragma unroll
    for (int j = 0; j < 8; j++) {
        int c4 = lane + j * 32;
        float4 x = ((const float4*)g_X)[(size_t)row * 256 + c4];
        float4 sc = ((const float4*)lns)[c4];
        float4 bi = ((const float4*)lnb)[c4];
        float4 o;
        o.x = (x.x - mean) * inv * sc.x + bi.x;
        o.y = (x.y - mean) * inv * sc.y + bi.y;
        o.z = (x.z - mean) * inv * sc.z + bi.z;
        o.w = (x.w - mean) * inv * sc.w + bi.w;
        ((float4*)out)[(size_t)row * 256 + c4] = o;
    }
}

// ---------------- launch: kernel launches ONLY ----------------
extern "C" void kernel_launch(void* const* d_in, const int* in_sizes, int n_in,
                              void* d_out, int out_size) {
    const float* hA    = (const float*)d_in[0];
    const float* pool  = (const float*)d_in[1];
    const float* alpha = (const float*)d_in[2];
    const float* W     = (const float*)d_in[3];
    const float* bb    = (const float*)d_in[4];
    const float* gamma = (const float*)d_in[5];
    const float* lns   = (const float*)d_in[6];
    const float* lnb   = (const float*)d_in[7];
    float* out = (float*)d_out;

    k0_kernel<<<145, 256>>>(hA, pool, alpha, W);
    k1_kernel<<<128, 256>>>(alpha);
    k2_kernel<<<128, 256>>>(hA, bb, gamma);
    ln_kernel<<<32, 256>>>(lns, lnb, out);
}

// round 11
// speedup vs baseline: 1.3089x; 1.3089x over previous
#include <cuda_runtime.h>
#include <cuda_bf16.h>
#include <cstdint>

#define D_A      1024
#define NEXP     64
#define BATCH    256
#define POOL_DIM 33792
#define U_END    16384
#define V_END    32768
#define KP       1152     /* padded row stride (elems) for bf16 S / BmatT */
#define LN_EPS   1e-5f

#define NK1 16            /* 1024/64 */
#define NK2 17            /* 1088/64 */
#define A_STG1 8192       /* 64 rows x 128B */
#define B_STG1 8192
#define A_STG2 4096       /* 32 rows x 128B */
#define B_STG2 8192       /* 64 rows x 128B */
#define EP 68             /* epilogue stage stride (floats) */

// ---------------- scratch ----------------
__device__ __align__(128) __nv_bfloat16 g_hA16[BATCH * D_A];            // 512KB
__device__ __align__(128) __nv_bfloat16 g_B1[(size_t)2048 * D_A];       // 4MB  [j][k]
__device__ __align__(128) __nv_bfloat16 g_BmatT16[(size_t)1024 * KP];   // 2.25MB [c][k]
__device__ __align__(128) __nv_bfloat16 g_S16[(size_t)BATCH * KP];      // 576KB [b][k]
__device__ __align__(128) float  g_P[BATCH * 1024];
__device__ __align__(128) float  g_X[BATCH * 1024];
__device__ __align__(128) float2 g_part[BATCH * 16];                    // [row][bn]

// ---------------- helpers ----------------
__device__ __forceinline__ uint32_t smem_u32(const void* p) {
    uint32_t a;
    asm("{ .reg .u64 t; cvta.to.shared.u64 t, %1; cvt.u32.u64 %0, t; }" : "=r"(a) : "l"(p));
    return a;
}
__device__ __forceinline__ uint32_t swz(uint32_t off) { return off ^ ((off >> 3) & 0x70); }
__device__ __forceinline__ void cpa16(uint32_t saddr, const void* g) {
    asm volatile("cp.async.cg.shared.global [%0], [%1], 16;\n" :: "r"(saddr), "l"(g));
}
__device__ __forceinline__ void cp_commit() { asm volatile("cp.async.commit_group;\n"); }
template<int N> __device__ __forceinline__ void cp_wait() {
    asm volatile("cp.async.wait_group %0;\n" :: "n"(N));
}
#define LDSM4(R, addr) \
    asm volatile("ldmatrix.sync.aligned.m8n8.x4.shared.b16 {%0,%1,%2,%3}, [%4];" \
        : "=r"((R)[0]), "=r"((R)[1]), "=r"((R)[2]), "=r"((R)[3]) : "r"(addr))
__device__ __forceinline__ void mma_bf16(float* c, const uint32_t* a, uint32_t b0, uint32_t b1) {
    asm volatile(
        "mma.sync.aligned.m16n8k16.row.col.f32.bf16.bf16.f32 "
        "{%0,%1,%2,%3}, {%4,%5,%6,%7}, {%8,%9}, {%0,%1,%2,%3};\n"
        : "+f"(c[0]), "+f"(c[1]), "+f"(c[2]), "+f"(c[3])
        : "r"(a[0]), "r"(a[1]), "r"(a[2]), "r"(a[3]), "r"(b0), "r"(b1));
}
__device__ __forceinline__ uint32_t pack_bf2(float x, float y) {
    __nv_bfloat162 h = __floats2bfloat162_rn(x, y);
    return *reinterpret_cast<uint32_t*>(&h);
}

// ---------------- k0: pure conversion (128 blocks x 256) --------------------
// block cid: 16 rows of g_B1 (W|V -> bf16) + 2 rows of g_hA16
__global__ void __launch_bounds__(256) k0_kernel(const float* __restrict__ hA,
                                                 const float* __restrict__ pool,
                                                 const float* __restrict__ W) {
    const int tid = threadIdx.x;
    const int cid = blockIdx.x;
    #pragma unroll 4
    for (int it = 0; it < 16; it++) {
        int e = tid + it * 256;
        int rr = e >> 8, i4 = e & 255;
        int j = cid * 16 + rr;
        const float* src = (j < 1024)
            ? (W + (size_t)j * D_A)
            : (pool + (size_t)((j - 1024) >> 4) * POOL_DIM + U_END + (size_t)((j - 1024) & 15) * D_A);
        float4 v = ((const float4*)src)[i4];
        *(uint2*)((char*)g_B1 + (size_t)j * 2048 + i4 * 8) =
            make_uint2(pack_bf2(v.x, v.y), pack_bf2(v.z, v.w));
    }
    #pragma unroll
    for (int it = 0; it < 2; it++) {
        int e = tid + it * 256;
        int rr = e >> 8, i4 = e & 255;
        int row = cid * 2 + rr;
        float4 v = ((const float4*)(hA + (size_t)row * D_A))[i4];
        *(uint2*)((char*)g_hA16 + (size_t)row * 2048 + i4 * 8) =
            make_uint2(pack_bf2(v.x, v.y), pack_bf2(v.z, v.w));
    }
}

// ---------------- prep role (17 blocks, inside k1's grid) -------------------
// pid 0..15: U transpose (64 c-rows) + bias cols -> g_BmatT16 ; pid 16: alpha
__device__ void prep_role(int pid, float* sf, const float* __restrict__ pool,
                          const float* __restrict__ alpha) {
    const int tid = threadIdx.x;
    if (pid == 16) {
        #pragma unroll 8
        for (int it = 0; it < 64; it++) {
            int e = tid + it * 256;
            int b = e >> 6, n = e & 63;
            g_S16[(size_t)b * KP + 1024 + n] = __float2bfloat16(alpha[b * NEXP + n]);
        }
        return;
    }
    for (int half = 0; half < 2; half++) {
        const int c0 = pid * 64 + half * 32;
        for (int ng = 0; ng < 4; ng++) {
            #pragma unroll
            for (int it = 0; it < 8; it++) {
                int e = tid + it * 256;
                int nl = e >> 7, i4 = e & 127;
                const float4* src = (const float4*)(pool + (size_t)(ng * 16 + nl) * POOL_DIM + c0 * 16) + i4;
                *(float4*)(sf + nl * 528 + i4 * 4) = *src;
            }
            __syncthreads();
            #pragma unroll 8
            for (int it = 0; it < 32; it++) {
                int e = tid + it * 256;
                int cl = e >> 8, j = e & 255;
                int nl = j >> 4, r = j & 15;
                g_BmatT16[(size_t)(c0 + cl) * KP + ng * 256 + j] =
                    __float2bfloat16(sf[nl * 528 + cl * 16 + r]);
            }
            __syncthreads();
        }
        #pragma unroll
        for (int it = 0; it < 8; it++) {
            int e = tid + it * 256;
            int n = e >> 5, cl = e & 31;
            sf[n * 33 + cl] = pool[(size_t)n * POOL_DIM + V_END + c0 + cl];
        }
        __syncthreads();
        #pragma unroll
        for (int it = 0; it < 8; it++) {
            int e = tid + it * 256;
            int cl = e >> 6, n = e & 63;
            g_BmatT16[(size_t)(c0 + cl) * KP + 1024 + n] = __float2bfloat16(sf[n * 33 + cl]);
        }
        __syncthreads();
    }
}

// ---------------- k1: blocks 0..16 prep; 17..144 GEMM1 bf16 64x64 -----------
// C[256,2048] = hA16 * g_B1^T ; cols<1024 -> g_P, cols>=1024 -> g_S16*alpha
__global__ void __launch_bounds__(256) k1_kernel(const float* __restrict__ pool,
                                                 const float* __restrict__ alpha) {
    __shared__ __align__(128) char smem_all[49152];   // 3 stages x (8K A + 8K B)
    const int bid = blockIdx.x;
    if (bid < 17) { prep_role(bid, (float*)smem_all, pool, alpha); return; }

    const uint32_t sb = smem_u32(smem_all);
    const int gb = bid - 17;
    const int bm = gb >> 5;          // 0..3
    const int bn = gb & 31;          // 0..31
    const int tid = threadIdx.x;
    const int lane = tid & 31, warp = tid >> 5;
    const int wm = warp & 1;          // 2 x 32 rows
    const int wn = warp >> 1;         // 4 x 16 cols
    const int g = lane >> 2, tig = lane & 3;

    const uint32_t sbA = sb;
    const uint32_t sbB = sb + 3 * A_STG1;

    const char* aSrc[2]; uint32_t aDst[2];
    const char* bSrc[2]; uint32_t bDst[2];
    #pragma unroll
    for (int q = 0; q < 2; q++) {
        int id = tid + q * 256;
        int row = id >> 3, c8 = id & 7;
        aSrc[q] = (const char*)g_hA16 + (size_t)(bm * 64 + row) * 2048 + c8 * 16;
        aDst[q] = swz(row * 128 + c8 * 16);
        bSrc[q] = (const char*)g_B1 + (size_t)(bn * 64 + row) * 2048 + c8 * 16;
        bDst[q] = aDst[q];
    }
    auto fill = [&](int s, int kc) {
        const int off = kc * 128;
        #pragma unroll
        for (int q = 0; q < 2; q++) {
            cpa16(sbA + s * A_STG1 + aDst[q], aSrc[q] + off);
            cpa16(sbB + s * B_STG1 + bDst[q], bSrc[q] + off);
        }
    };

    uint32_t aBase[2], aXor[2], bBase, bXor;
    const uint32_t half16 = ((lane >> 4) & 1) * 16;
    #pragma unroll
    for (int im = 0; im < 2; im++) {
        int r = wm * 32 + im * 16 + (lane & 15);
        aBase[im] = r * 128; aXor[im] = (r & 7) << 4;
    }
    {
        int r = wn * 16 + (lane & 15);
        bBase = r * 128; bXor = (r & 7) << 4;
    }

    float acc[2][2][4];
    #pragma unroll
    for (int i = 0; i < 2; i++)
        #pragma unroll
        for (int j = 0; j < 2; j++)
            #pragma unroll
            for (int e = 0; e < 4; e++) acc[i][j][e] = 0.f;

    fill(0, 0); cp_commit(); fill(1, 1); cp_commit();

    int s = 0;
    for (int i = 0; i < NK1; i++) {
        cp_wait<1>();
        __syncthreads();
        if (i + 2 < NK1) fill((i + 2) % 3, i + 2);
        cp_commit();
        const uint32_t sA = sbA + s * A_STG1;
        const uint32_t sB = sbB + s * B_STG1;
        #pragma unroll
        for (int kk = 0; kk < 4; kk++) {
            uint32_t a[2][4], bq[4];
            #pragma unroll
            for (int im = 0; im < 2; im++)
                LDSM4(a[im], sA + aBase[im] + ((kk * 32 + half16) ^ aXor[im]));
            LDSM4(bq, sB + bBase + ((kk * 32 + half16) ^ bXor));
            #pragma unroll
            for (int im = 0; im < 2; im++) {
                mma_bf16(acc[im][0], a[im], bq[0], bq[2]);
                mma_bf16(acc[im][1], a[im], bq[1], bq[3]);
            }
        }
        s = (s == 2) ? 0 : s + 1;
    }
    __syncthreads();

    float* se = (float*)smem_all;
    #pragma unroll
    for (int im = 0; im < 2; im++)
        #pragma unroll
        for (int jb = 0; jb < 2; jb++) {
            int r0 = wm * 32 + im * 16 + g;
            int c  = wn * 16 + jb * 8 + 2 * tig;
            se[r0 * EP + c]           = acc[im][jb][0];
            se[r0 * EP + c + 1]       = acc[im][jb][1];
            se[(r0 + 8) * EP + c]     = acc[im][jb][2];
            se[(r0 + 8) * EP + c + 1] = acc[im][jb][3];
        }
    __syncthreads();
    #pragma unroll
    for (int it = 0; it < 4; it++) {
        int id = tid + it * 256;
        int row = id >> 4, c4 = id & 15;
        float4 v = *(const float4*)(se + row * EP + c4 * 4);
        int rowg = bm * 64 + row;
        if (bn < 16) {
            ((float4*)g_P)[(size_t)rowg * 256 + bn * 16 + c4] = v;
        } else {
            int n = (bn - 16) * 4 + (c4 >> 2);
            float a = alpha[rowg * NEXP + n];
            *(uint2*)((char*)g_S16 + ((size_t)rowg * KP + (bn - 16) * 64 + c4 * 4) * 2) =
                make_uint2(pack_bf2(v.x * a, v.y * a), pack_bf2(v.z * a, v.w * a));
        }
    }
}

// ---------------- k2: GEMM2 bf16, 32x64 tiles, 128 CTAs ---------------------
// X = hA + gamma*(S16 @ BmatT16^T + P + b_base)
__global__ void __launch_bounds__(256) k2_kernel(const float* __restrict__ hA,
                                                 const float* __restrict__ bbase,
                                                 const float* __restrict__ gamma_p) {
    __shared__ __align__(128) char smem_all[49152];   // 4 stages x (4K A + 8K B)
    const uint32_t sb = smem_u32(smem_all);
    const int bid = blockIdx.x;
    const int bm = bid >> 4;          // 0..7 (32-row tiles)
    const int bn = bid & 15;          // 0..15 (64-col tiles)
    const int tid = threadIdx.x;
    const int lane = tid & 31, warp = tid >> 5;
    const int wm = warp & 1;          // 2 x 16 rows
    const int wn = warp >> 1;         // 4 x 16 cols
    const int g = lane >> 2, tig = lane & 3;

    const uint32_t sbA = sb;
    const uint32_t sbB = sb + 4 * A_STG2;

    const char* aSrc; uint32_t aDst;
    {
        int row = tid >> 3, c8 = tid & 7;
        aSrc = (const char*)g_S16 + (size_t)(bm * 32 + row) * (KP * 2) + c8 * 16;
        aDst = swz(row * 128 + c8 * 16);
    }
    const char* bSrc[2]; uint32_t bDst[2];
    #pragma unroll
    for (int q = 0; q < 2; q++) {
        int id = tid + q * 256;
        int row = id >> 3, c8 = id & 7;
        bSrc[q] = (const char*)g_BmatT16 + (size_t)(bn * 64 + row) * (KP * 2) + c8 * 16;
        bDst[q] = swz(row * 128 + c8 * 16);
    }
    auto fill = [&](int s, int kc) {
        const int off = kc * 128;
        cpa16(sbA + s * A_STG2 + aDst, aSrc + off);
        #pragma unroll
        for (int q = 0; q < 2; q++)
            cpa16(sbB + s * B_STG2 + bDst[q], bSrc[q] + off);
    };

    uint32_t aBase, aXor, bBase, bXor;
    const uint32_t half16 = ((lane >> 4) & 1) * 16;
    {
        int r = wm * 16 + (lane & 15);
        aBase = r * 128; aXor = (r & 7) << 4;
    }
    {
        int r = wn * 16 + (lane & 15);
        bBase = r * 128; bXor = (r & 7) << 4;
    }

    float acc[2][4];
    #pragma unroll
    for (int j = 0; j < 2; j++)
        #pragma unroll
        for (int e = 0; e < 4; e++) acc[j][e] = 0.f;

    fill(0, 0); cp_commit(); fill(1, 1); cp_commit(); fill(2, 2); cp_commit();

    for (int i = 0; i < NK2; i++) {
        cp_wait<2>();
        __syncthreads();
        if (i + 3 < NK2) fill((i + 3) & 3, i + 3);
        cp_commit();
        const int s = i & 3;
        const uint32_t sA = sbA + s * A_STG2;
        const uint32_t sB = sbB + s * B_STG2;
        #pragma unroll
        for (int kk = 0; kk < 4; kk++) {
            uint32_t a[4], bq[4];
            LDSM4(a, sA + aBase + ((kk * 32 + half16) ^ aXor));
            LDSM4(bq, sB + bBase + ((kk * 32 + half16) ^ bXor));
            mma_bf16(acc[0], a, bq[0], bq[2]);
            mma_bf16(acc[1], a, bq[1], bq[3]);
        }
    }
    __syncthreads();

    float* se = (float*)smem_all;
    #pragma unroll
    for (int jb = 0; jb < 2; jb++) {
        int r0 = wm * 16 + g;
        int c  = wn * 16 + jb * 8 + 2 * tig;
        se[r0 * EP + c]           = acc[jb][0];
        se[r0 * EP + c + 1]       = acc[jb][1];
        se[(r0 + 8) * EP + c]     = acc[jb][2];
        se[(r0 + 8) * EP + c + 1] = acc[jb][3];
    }
    __syncthreads();
    const float gam = *gamma_p;
    #pragma unroll
    for (int it = 0; it < 2; it++) {
        int id = tid + it * 256;
        int row = id >> 4, c4 = id & 15;
        float4 v = *(const float4*)(se + row * EP + c4 * 4);
        int rowg = bm * 32 + row;
        int cc4 = bn * 16 + c4;
        float4 p4 = ((const float4*)g_P)[(size_t)rowg * 256 + cc4];
        float4 b4 = ((const float4*)bbase)[cc4];
        float4 h4 = ((const float4*)hA)[(size_t)rowg * 256 + cc4];
        float4 x;
        x.x = h4.x + gam * (v.x + p4.x + b4.x);
        x.y = h4.y + gam * (v.y + p4.y + b4.y);
        x.z = h4.z + gam * (v.z + p4.z + b4.z);
        x.w = h4.w + gam * (v.w + p4.w + b4.w);
        ((float4*)g_X)[(size_t)rowg * 256 + cc4] = x;
        float s2  = x.x + x.y + x.z + x.w;
        float ss2 = x.x * x.x + x.y * x.y + x.z * x.z + x.w * x.w;
        #pragma unroll
        for (int off = 8; off; off >>= 1) {
            s2  += __shfl_xor_sync(0xffffffffu, s2, off);
            ss2 += __shfl_xor_sync(0xffffffffu, ss2, off);
        }
        if ((tid & 15) == 0) g_part[rowg * 16 + bn] = make_float2(s2, ss2);
    }
}

// ---------------- LayerNorm: one row per block, 256 blocks ------------------
__global__ void __launch_bounds__(128) ln_kernel(const float* __restrict__ lns,
                                                 const float* __restrict__ lnb,
                                                 float* __restrict__ out) {
    const int row = blockIdx.x;
    const int tid = threadIdx.x;
    const int lane = tid & 31;
    __shared__ float mv[2];
    if (tid < 32) {
        float s = 0.f, ss = 0.f;
        if (lane < 16) {
            float2 p = g_part[row * 16 + lane];
            s = p.x; ss = p.y;
        }
        #pragma unroll
        for (int off = 8; off; off >>= 1) {
            s  += __shfl_xor_sync(0xffffffffu, s, off);
            ss += __shfl_xor_sync(0xffffffffu, ss, off);
        }
        s  += __shfl_xor_sync(0xffffffffu, s, 16);
        ss += __shfl_xor_sync(0xffffffffu, ss, 16);
        if (lane == 0) {
            float mean = s * (1.f / 1024.f);
            mv[0] = mean;
            mv[1] = rsqrtf(ss * (1.f / 1024.f) - mean * mean + LN_EPS);
        }
    }
    __syncthreads();
    const float mean = mv[0], inv = mv[1];
    #pragma unroll
    for (int j = 0; j < 2; j++) {
        int c4 = tid + j * 128;
        float4 x = ((const float4*)g_X)[(size_t)row * 256 + c4];
        float4 sc = ((const float4*)lns)[c4];
        float4 bi = ((const float4*)lnb)[c4];
        float4 o;
        o.x = (x.x - mean) * inv * sc.x + bi.x;
        o.y = (x.y - mean) * inv * sc.y + bi.y;
        o.z = (x.z - mean) * inv * sc.z + bi.z;
        o.w = (x.w - mean) * inv * sc.w + bi.w;
        ((float4*)out)[(size_t)row * 256 + c4] = o;
    }
}

// ---------------- launch: kernel launches ONLY ----------------
extern "C" void kernel_launch(void* const* d_in, const int* in_sizes, int n_in,
                              void* d_out, int out_size) {
    const float* hA    = (const float*)d_in[0];
    const float* pool  = (const float*)d_in[1];
    const float* alpha = (const float*)d_in[2];
    const float* W     = (const float*)d_in[3];
    const float* bb    = (const float*)d_in[4];
    const float* gamma = (const float*)d_in[5];
    const float* lns   = (const float*)d_in[6];
    const float* lnb   = (const float*)d_in[7];
    float* out = (float*)d_out;

    k0_kernel<<<128, 256>>>(hA, pool, W);
    k1_kernel<<<145, 256>>>(pool, alpha);
    k2_kernel<<<128, 256>>>(hA, bb, gamma);
    ln_kernel<<<256, 128>>>(lns, lnb, out);
}